// round 1
// baseline (speedup 1.0000x reference)
#include <cuda_runtime.h>
#include <cuda_bf16.h>
#include <math.h>

// ---------------------------------------------------------------------------
// QuantumAttention: analytic collapse of the 8-qubit circuit.
//   z_i = cos(x_i + p_i)
//   proj[0]    = z1*z2*...*z7
//   proj[w>=1] = z0*z1*...*zw
// Then per-head attention (64 heads, S=1024, d=8), softmax WITHOUT max
// (|score| <= sqrt(8) ~ 2.83, safely inside expf range), then out @ W^T.
// ---------------------------------------------------------------------------

#define NROWS   65536      // B*S*H = 4*1024*16
#define S_LEN   1024
#define NHEADS  64         // B*H
#define DK      8
#define E_DIM   128
#define NROWS_E 4096       // B*S

__device__ float g_qkv[NROWS * DK];     // [b,h,s,d] head-major
__device__ float g_attn[NROWS_E * E_DIM]; // [b,s,e] row-major attention output
__device__ float g_wt[E_DIM * E_DIM];   // W transposed: Wt[f*128+e] = W[e*128+f]

// ---- packed f32x2 helpers (full-rate fp32 FMA on Blackwell) ----
typedef unsigned long long ull;

__device__ __forceinline__ ull fma2(ull a, ull b, ull c) {
    ull d;
    asm("fma.rn.f32x2 %0, %1, %2, %3;" : "=l"(d) : "l"(a), "l"(b), "l"(c));
    return d;
}
__device__ __forceinline__ ull mul2(ull a, ull b) {
    ull d;
    asm("mul.rn.f32x2 %0, %1, %2;" : "=l"(d) : "l"(a), "l"(b));
    return d;
}
__device__ __forceinline__ ull pack2(float x, float y) {
    ull r;
    asm("mov.b64 %0, {%1, %2};" : "=l"(r) : "f"(x), "f"(y));
    return r;
}
__device__ __forceinline__ void unpack2(ull v, float& x, float& y) {
    asm("mov.b64 {%0, %1}, %2;" : "=f"(x), "=f"(y) : "l"(v));
}

// ---------------------------------------------------------------------------
// Kernel 1: quantum projection (cos + prefix products), write head-major
// ---------------------------------------------------------------------------
__global__ void qkv_kernel(const float* __restrict__ x,
                           const float* __restrict__ rx) {
    int r = blockIdx.x * blockDim.x + threadIdx.x;   // row in [0, 65536)
    if (r >= NROWS) return;

    float pv[8];
#pragma unroll
    for (int i = 0; i < 8; i++) pv[i] = __ldg(rx + i);

    const float4* xr = reinterpret_cast<const float4*>(x + (size_t)r * DK);
    float4 x0 = xr[0];
    float4 x1 = xr[1];

    float z0 = cosf(x0.x + pv[0]);
    float z1 = cosf(x0.y + pv[1]);
    float z2 = cosf(x0.z + pv[2]);
    float z3 = cosf(x0.w + pv[3]);
    float z4 = cosf(x1.x + pv[4]);
    float z5 = cosf(x1.y + pv[5]);
    float z6 = cosf(x1.z + pv[6]);
    float z7 = cosf(x1.w + pv[7]);

    float o1 = z0 * z1;
    float o2 = o1 * z2;
    float o3 = o2 * z3;
    float o4 = o3 * z4;
    float o5 = o4 * z5;
    float o6 = o5 * z6;
    float o7 = o6 * z7;
    // o0 = z1*...*z7
    float o0 = z1 * z2;
    o0 *= z3; o0 *= z4; o0 *= z5; o0 *= z6; o0 *= z7;

    // r = (b*1024 + s)*16 + h  ->  dst row = (b*16 + h)*1024 + s
    int h  = r & 15;
    int bs = r >> 4;
    int b  = bs >> 10;
    int s  = bs & 1023;
    int dst = ((b << 4) + h) * S_LEN + s;

    float4* out = reinterpret_cast<float4*>(g_qkv + (size_t)dst * DK);
    out[0] = make_float4(o0, o1, o2, o3);
    out[1] = make_float4(o4, o5, o6, o7);
}

// ---------------------------------------------------------------------------
// Kernel 2: per-head attention. One thread = one query; K tile in shared.
// Single-pass softmax (no max subtraction needed: |s| <= 2.83).
// ---------------------------------------------------------------------------
#define QT 8   // query tiles per head (1024 / 128 threads)

__global__ __launch_bounds__(128) void attn_kernel() {
    __shared__ __align__(16) float sK[S_LEN * DK];   // 32 KB

    int head = blockIdx.x >> 3;
    int qt   = blockIdx.x & 7;
    const float* Kg = g_qkv + (size_t)head * S_LEN * DK;

    // cooperative coalesced load of the head's K/V (8192 floats = 2048 float4)
    const float4* Kg4 = reinterpret_cast<const float4*>(Kg);
    float4* sK4 = reinterpret_cast<float4*>(sK);
#pragma unroll
    for (int i = threadIdx.x; i < 2048; i += 128) sK4[i] = Kg4[i];
    __syncthreads();

    int q = qt * 128 + threadIdx.x;
    const float inv = 0.35355339059327373f;   // 1/sqrt(8)

    const float* qrow = sK + q * DK;
    ull q01 = pack2(qrow[0] * inv, qrow[1] * inv);
    ull q23 = pack2(qrow[2] * inv, qrow[3] * inv);
    ull q45 = pack2(qrow[4] * inv, qrow[5] * inv);
    ull q67 = pack2(qrow[6] * inv, qrow[7] * inv);

    ull acc0 = 0ull, acc1 = 0ull, acc2 = 0ull, acc3 = 0ull;
    float l = 0.0f;

    const ulonglong2* Ks = reinterpret_cast<const ulonglong2*>(sK);
#pragma unroll 4
    for (int k = 0; k < S_LEN; k++) {
        ulonglong2 ka = Ks[2 * k];
        ulonglong2 kb = Ks[2 * k + 1];
        ull d = fma2(q01, ka.x, fma2(q23, ka.y, fma2(q45, kb.x, mul2(q67, kb.y))));
        float dlo, dhi;
        unpack2(d, dlo, dhi);
        float p = __expf(dlo + dhi);
        l += p;
        ull p2 = pack2(p, p);
        acc0 = fma2(p2, ka.x, acc0);
        acc1 = fma2(p2, ka.y, acc1);
        acc2 = fma2(p2, kb.x, acc2);
        acc3 = fma2(p2, kb.y, acc3);
    }

    float rl = 1.0f / l;
    float a0, a1, a2, a3, a4, a5, a6, a7;
    unpack2(acc0, a0, a1);
    unpack2(acc1, a2, a3);
    unpack2(acc2, a4, a5);
    unpack2(acc3, a6, a7);

    int b = head >> 4;
    int h = head & 15;
    float* o = g_attn + ((size_t)((b << 10) + q) * E_DIM) + h * DK;
    float4* o4 = reinterpret_cast<float4*>(o);
    o4[0] = make_float4(a0 * rl, a1 * rl, a2 * rl, a3 * rl);
    o4[1] = make_float4(a4 * rl, a5 * rl, a6 * rl, a7 * rl);
}

// ---------------------------------------------------------------------------
// Kernel 3a: transpose combine_w so combine reads are coalesced.
// ---------------------------------------------------------------------------
__global__ void transpose_w(const float* __restrict__ W) {
    int j = blockIdx.x * blockDim.x + threadIdx.x;   // j = f*128 + e
    if (j >= E_DIM * E_DIM) return;
    int f = j >> 7;
    int e = j & 127;
    g_wt[j] = __ldg(W + e * E_DIM + f);
}

// ---------------------------------------------------------------------------
// Kernel 3b: out[row, e] = sum_f attn[row, f] * W[e, f] = sum_f a[f]*Wt[f,e]
// ---------------------------------------------------------------------------
__global__ __launch_bounds__(128) void combine_kernel(float* __restrict__ out) {
    __shared__ float a[E_DIM];
    int row = blockIdx.x;
    int t = threadIdx.x;
    a[t] = g_attn[(size_t)row * E_DIM + t];
    __syncthreads();

    float acc = 0.0f;
#pragma unroll
    for (int f = 0; f < E_DIM; f++) {
        acc = fmaf(a[f], g_wt[f * E_DIM + t], acc);
    }
    out[(size_t)row * E_DIM + t] = acc;
}

// ---------------------------------------------------------------------------
extern "C" void kernel_launch(void* const* d_in, const int* in_sizes, int n_in,
                              void* d_out, int out_size) {
    // defensive input mapping by element count (sizes are all distinct)
    const float* x  = nullptr;
    const float* rx = nullptr;
    const float* cw = nullptr;
    for (int i = 0; i < n_in; i++) {
        if (in_sizes[i] == NROWS * DK)          x  = (const float*)d_in[i];
        else if (in_sizes[i] == DK)             rx = (const float*)d_in[i];
        else if (in_sizes[i] == E_DIM * E_DIM)  cw = (const float*)d_in[i];
    }
    if (!x)  x  = (const float*)d_in[0];
    if (!rx) rx = (const float*)d_in[1];
    if (!cw) cw = (const float*)d_in[2];

    float* out = (float*)d_out;

    qkv_kernel<<<NROWS / 256, 256>>>(x, rx);
    transpose_w<<<(E_DIM * E_DIM + 255) / 256, 256>>>(cw);
    attn_kernel<<<NHEADS * QT, 128>>>();
    combine_kernel<<<NROWS_E, 128>>>(out);
}

// round 3
// speedup vs baseline: 1.1751x; 1.1751x over previous
#include <cuda_runtime.h>
#include <cuda_bf16.h>
#include <math.h>

// ---------------------------------------------------------------------------
// QuantumAttention: analytic collapse of the 8-qubit circuit.
//   z_i = cos(x_i + p_i)
//   proj[0]    = z1*...*z7 ; proj[w>=1] = z0*...*zw
// Then per-head attention (64 heads, S=1024, d=8), softmax without max
// (|score| <= 2.83), then out @ W^T.
// ---------------------------------------------------------------------------

#define NROWS   65536      // B*S*H
#define S_LEN   1024
#define NHEADS  64         // B*H
#define DK      8
#define E_DIM   128
#define NROWS_E 4096       // B*S

__device__ float g_qkv[NROWS * DK];       // [b,h,s,d] head-major
__device__ float g_attn[NROWS_E * E_DIM]; // [b,s,e] attention output
__device__ float g_wt[E_DIM * E_DIM];     // Wt[f*128+e] = W[e*128+f]

typedef unsigned long long ull;

__device__ __forceinline__ ull fma2(ull a, ull b, ull c) {
    ull d;
    asm("fma.rn.f32x2 %0, %1, %2, %3;" : "=l"(d) : "l"(a), "l"(b), "l"(c));
    return d;
}
__device__ __forceinline__ ull mul2(ull a, ull b) {
    ull d;
    asm("mul.rn.f32x2 %0, %1, %2;" : "=l"(d) : "l"(a), "l"(b));
    return d;
}
__device__ __forceinline__ ull add2(ull a, ull b) {
    ull d;
    asm("add.rn.f32x2 %0, %1, %2;" : "=l"(d) : "l"(a), "l"(b));
    return d;
}
__device__ __forceinline__ ull pack2(float x, float y) {
    ull r;
    asm("mov.b64 %0, {%1, %2};" : "=l"(r) : "f"(x), "f"(y));
    return r;
}
__device__ __forceinline__ void unpack2(ull v, float& x, float& y) {
    asm("mov.b64 {%0, %1}, %2;" : "=f"(x), "=f"(y) : "l"(v));
}
__device__ __forceinline__ float ex2(float x) {
    float y;
    asm("ex2.approx.ftz.f32 %0, %1;" : "=f"(y) : "f"(x));
    return y;
}

// ---------------------------------------------------------------------------
// Kernel 1: quantum projection (cos + prefix products), head-major output
// ---------------------------------------------------------------------------
__global__ void qkv_kernel(const float* __restrict__ x,
                           const float* __restrict__ rx) {
    int r = blockIdx.x * blockDim.x + threadIdx.x;
    if (r >= NROWS) return;

    float pv[8];
#pragma unroll
    for (int i = 0; i < 8; i++) pv[i] = __ldg(rx + i);

    const float4* xr = reinterpret_cast<const float4*>(x + (size_t)r * DK);
    float4 x0 = xr[0];
    float4 x1 = xr[1];

    float z0 = __cosf(x0.x + pv[0]);
    float z1 = __cosf(x0.y + pv[1]);
    float z2 = __cosf(x0.z + pv[2]);
    float z3 = __cosf(x0.w + pv[3]);
    float z4 = __cosf(x1.x + pv[4]);
    float z5 = __cosf(x1.y + pv[5]);
    float z6 = __cosf(x1.z + pv[6]);
    float z7 = __cosf(x1.w + pv[7]);

    float o1 = z0 * z1;
    float o2 = o1 * z2;
    float o3 = o2 * z3;
    float o4 = o3 * z4;
    float o5 = o4 * z5;
    float o6 = o5 * z6;
    float o7 = o6 * z7;
    float o0 = z1 * z2;
    o0 *= z3; o0 *= z4; o0 *= z5; o0 *= z6; o0 *= z7;

    int h  = r & 15;
    int bs = r >> 4;
    int b  = bs >> 10;
    int s  = bs & 1023;
    int dst = ((b << 4) + h) * S_LEN + s;

    float4* out = reinterpret_cast<float4*>(g_qkv + (size_t)dst * DK);
    out[0] = make_float4(o0, o1, o2, o3);
    out[1] = make_float4(o4, o5, o6, o7);
}

// ---------------------------------------------------------------------------
// Kernel 2: attention. K stored in shared in k-PAIR-interleaved layout:
//   word(j, d) = ( K[2j][d] , K[2j+1][d] )   as f32x2
// Dot products for two keys run in the two f32x2 lanes -> no horizontal
// add per pair; q pre-scaled by log2e/sqrt(8) -> raw ex2 for softmax.
// ---------------------------------------------------------------------------
__global__ __launch_bounds__(128) void attn_kernel() {
    __shared__ __align__(16) float sK[S_LEN * DK];   // 32 KB, permuted

    int head = blockIdx.x >> 3;
    int qt   = blockIdx.x & 7;

    const float4* Kg4 = reinterpret_cast<const float4*>(g_qkv + (size_t)head * S_LEN * DK);
#pragma unroll
    for (int i = threadIdx.x; i < 2048; i += 128) {
        float4 v = Kg4[i];
        int r  = i >> 1;                 // source row
        int dh = (i & 1) << 2;           // d base: 0 or 4
        int pr = r >> 1;                 // pair index
        int ln = r & 1;                  // lane within pair
        float* dst = sK + ((pr << 3) + dh) * 2 + ln;
        dst[0] = v.x; dst[2] = v.y; dst[4] = v.z; dst[6] = v.w;
    }
    __syncthreads();

    int q  = qt * 128 + threadIdx.x;
    int pq = q >> 1;
    int lq = q & 1;
    const float scale = 0.35355339059327373f * 1.4426950408889634f; // log2e/sqrt8

    ull q2[8];
#pragma unroll
    for (int d = 0; d < 8; d++) {
        float qa = sK[((pq << 3) + d) * 2 + lq] * scale;
        q2[d] = pack2(qa, qa);
    }

    ull t0 = 0, t1 = 0, t2 = 0, t3 = 0, t4 = 0, t5 = 0, t6 = 0, t7 = 0;
    ull l2 = 0;

    const ulonglong2* Ks = reinterpret_cast<const ulonglong2*>(sK);
#pragma unroll 2
    for (int j = 0; j < S_LEN / 2; j++) {
        ulonglong2 e0 = Ks[j * 4 + 0];
        ulonglong2 e1 = Ks[j * 4 + 1];
        ulonglong2 e2 = Ks[j * 4 + 2];
        ulonglong2 e3 = Ks[j * 4 + 3];

        ull d2 = mul2(q2[0], e0.x);
        d2 = fma2(q2[1], e0.y, d2);
        d2 = fma2(q2[2], e1.x, d2);
        d2 = fma2(q2[3], e1.y, d2);
        d2 = fma2(q2[4], e2.x, d2);
        d2 = fma2(q2[5], e2.y, d2);
        d2 = fma2(q2[6], e3.x, d2);
        d2 = fma2(q2[7], e3.y, d2);

        float s0, s1;
        unpack2(d2, s0, s1);
        float p0 = ex2(s0);
        float p1 = ex2(s1);
        ull p01 = pack2(p0, p1);

        l2 = add2(l2, p01);
        t0 = fma2(p01, e0.x, t0);
        t1 = fma2(p01, e0.y, t1);
        t2 = fma2(p01, e1.x, t2);
        t3 = fma2(p01, e1.y, t3);
        t4 = fma2(p01, e2.x, t4);
        t5 = fma2(p01, e2.y, t5);
        t6 = fma2(p01, e3.x, t6);
        t7 = fma2(p01, e3.y, t7);
    }

    float llo, lhi;
    unpack2(l2, llo, lhi);
    float rl = 1.0f / (llo + lhi);

    float a, b2;
    float o[8];
    unpack2(t0, a, b2); o[0] = (a + b2) * rl;
    unpack2(t1, a, b2); o[1] = (a + b2) * rl;
    unpack2(t2, a, b2); o[2] = (a + b2) * rl;
    unpack2(t3, a, b2); o[3] = (a + b2) * rl;
    unpack2(t4, a, b2); o[4] = (a + b2) * rl;
    unpack2(t5, a, b2); o[5] = (a + b2) * rl;
    unpack2(t6, a, b2); o[6] = (a + b2) * rl;
    unpack2(t7, a, b2); o[7] = (a + b2) * rl;

    int b = head >> 4;
    int h = head & 15;
    float4* o4 = reinterpret_cast<float4*>(
        g_attn + ((size_t)((b << 10) + q) * E_DIM) + h * DK);
    o4[0] = make_float4(o[0], o[1], o[2], o[3]);
    o4[1] = make_float4(o[4], o[5], o[6], o[7]);
}

// ---------------------------------------------------------------------------
// Kernel 3a: transpose combine_w (coalesced reads in combine)
// ---------------------------------------------------------------------------
__global__ void transpose_w(const float* __restrict__ W) {
    int j = blockIdx.x * blockDim.x + threadIdx.x;
    if (j >= E_DIM * E_DIM) return;
    int f = j >> 7;
    int e = j & 127;
    g_wt[j] = __ldg(W + e * E_DIM + f);
}

// ---------------------------------------------------------------------------
// Kernel 3b: 16 rows per block -> W traffic /16, 16 FMA per W load.
// ---------------------------------------------------------------------------
#define R_ROWS 16
__global__ __launch_bounds__(128) void combine_kernel(float* __restrict__ out) {
    __shared__ __align__(16) float sa[R_ROWS * E_DIM];  // 8 KB
    int row0 = blockIdx.x * R_ROWS;
    int t = threadIdx.x;

    const float4* src = reinterpret_cast<const float4*>(g_attn + (size_t)row0 * E_DIM);
    float4* sa4 = reinterpret_cast<float4*>(sa);
#pragma unroll
    for (int i = t; i < R_ROWS * E_DIM / 4; i += 128) sa4[i] = src[i];
    __syncthreads();

    float acc[R_ROWS];
#pragma unroll
    for (int r = 0; r < R_ROWS; r++) acc[r] = 0.0f;

#pragma unroll 4
    for (int f = 0; f < E_DIM; f++) {
        float w = __ldg(g_wt + f * E_DIM + t);
#pragma unroll
        for (int r = 0; r < R_ROWS; r++)
            acc[r] = fmaf(sa[r * E_DIM + f], w, acc[r]);
    }

#pragma unroll
    for (int r = 0; r < R_ROWS; r++)
        out[(size_t)(row0 + r) * E_DIM + t] = acc[r];
}

// ---------------------------------------------------------------------------
extern "C" void kernel_launch(void* const* d_in, const int* in_sizes, int n_in,
                              void* d_out, int out_size) {
    const float* x  = nullptr;
    const float* rx = nullptr;
    const float* cw = nullptr;
    for (int i = 0; i < n_in; i++) {
        if (in_sizes[i] == NROWS * DK)          x  = (const float*)d_in[i];
        else if (in_sizes[i] == DK)             rx = (const float*)d_in[i];
        else if (in_sizes[i] == E_DIM * E_DIM)  cw = (const float*)d_in[i];
    }
    if (!x)  x  = (const float*)d_in[0];
    if (!rx) rx = (const float*)d_in[1];
    if (!cw) cw = (const float*)d_in[2];

    float* out = (float*)d_out;

    qkv_kernel<<<NROWS / 256, 256>>>(x, rx);
    transpose_w<<<(E_DIM * E_DIM + 255) / 256, 256>>>(cw);
    attn_kernel<<<NHEADS * 8, 128>>>();
    combine_kernel<<<NROWS_E / R_ROWS, 128>>>(out);
}

// round 4
// speedup vs baseline: 1.2256x; 1.0430x over previous
#include <cuda_runtime.h>
#include <cuda_bf16.h>
#include <math.h>

// ---------------------------------------------------------------------------
// QuantumAttention: analytic collapse of the 8-qubit circuit.
//   z_i = cos(x_i + p_i)
//   proj[0]    = z1*...*z7 ; proj[w>=1] = z0*...*zw
// Then per-head attention (64 heads, S=1024, d=8), softmax without max
// (|score| <= 2.83), then out @ W^T.
// ---------------------------------------------------------------------------

#define NROWS   65536      // B*S*H
#define S_LEN   1024
#define NHEADS  64         // B*H
#define DK      8
#define E_DIM   128
#define NROWS_E 4096       // B*S

__device__ float g_qkv[NROWS * DK];       // [b,h,s,d] head-major
__device__ float g_attn[NROWS_E * E_DIM]; // [b,s,e] attention output
__device__ float g_wt[E_DIM * E_DIM];     // Wt[f*128+e] = W[e*128+f]

typedef unsigned long long ull;

__device__ __forceinline__ ull fma2(ull a, ull b, ull c) {
    ull d;
    asm("fma.rn.f32x2 %0, %1, %2, %3;" : "=l"(d) : "l"(a), "l"(b), "l"(c));
    return d;
}
__device__ __forceinline__ ull mul2(ull a, ull b) {
    ull d;
    asm("mul.rn.f32x2 %0, %1, %2;" : "=l"(d) : "l"(a), "l"(b));
    return d;
}
__device__ __forceinline__ ull add2(ull a, ull b) {
    ull d;
    asm("add.rn.f32x2 %0, %1, %2;" : "=l"(d) : "l"(a), "l"(b));
    return d;
}
__device__ __forceinline__ ull pack2(float x, float y) {
    ull r;
    asm("mov.b64 %0, {%1, %2};" : "=l"(r) : "f"(x), "f"(y));
    return r;
}
__device__ __forceinline__ void unpack2(ull v, float& x, float& y) {
    asm("mov.b64 {%0, %1}, %2;" : "=f"(x), "=f"(y) : "l"(v));
}
__device__ __forceinline__ float ex2(float x) {
    float y;
    asm("ex2.approx.ftz.f32 %0, %1;" : "=f"(y) : "f"(x));
    return y;
}

// ---------------------------------------------------------------------------
// Kernel 1: quantum projection (cos + prefix products), head-major output
// ---------------------------------------------------------------------------
__global__ void qkv_kernel(const float* __restrict__ x,
                           const float* __restrict__ rx) {
    int r = blockIdx.x * blockDim.x + threadIdx.x;
    if (r >= NROWS) return;

    float pv[8];
#pragma unroll
    for (int i = 0; i < 8; i++) pv[i] = __ldg(rx + i);

    const float4* xr = reinterpret_cast<const float4*>(x + (size_t)r * DK);
    float4 x0 = xr[0];
    float4 x1 = xr[1];

    float z0 = __cosf(x0.x + pv[0]);
    float z1 = __cosf(x0.y + pv[1]);
    float z2 = __cosf(x0.z + pv[2]);
    float z3 = __cosf(x0.w + pv[3]);
    float z4 = __cosf(x1.x + pv[4]);
    float z5 = __cosf(x1.y + pv[5]);
    float z6 = __cosf(x1.z + pv[6]);
    float z7 = __cosf(x1.w + pv[7]);

    float o1 = z0 * z1;
    float o2 = o1 * z2;
    float o3 = o2 * z3;
    float o4 = o3 * z4;
    float o5 = o4 * z5;
    float o6 = o5 * z6;
    float o7 = o6 * z7;
    float o0 = z1 * z2;
    o0 *= z3; o0 *= z4; o0 *= z5; o0 *= z6; o0 *= z7;

    int h  = r & 15;
    int bs = r >> 4;
    int b  = bs >> 10;
    int s  = bs & 1023;
    int dst = ((b << 4) + h) * S_LEN + s;

    float4* out = reinterpret_cast<float4*>(g_qkv + (size_t)dst * DK);
    out[0] = make_float4(o0, o1, o2, o3);
    out[1] = make_float4(o4, o5, o6, o7);
}

// ---------------------------------------------------------------------------
// Kernel 2: attention. K stored in shared in k-PAIR-interleaved layout:
//   word(j, d) = ( K[2j][d] , K[2j+1][d] )   as f32x2
// Dot products for two keys run in the two f32x2 lanes -> no horizontal
// add per pair; q pre-scaled by log2e/sqrt(8) -> raw ex2 for softmax.
// ---------------------------------------------------------------------------
__global__ __launch_bounds__(128) void attn_kernel() {
    __shared__ __align__(16) float sK[S_LEN * DK];   // 32 KB, permuted

    int head = blockIdx.x >> 3;
    int qt   = blockIdx.x & 7;

    const float4* Kg4 = reinterpret_cast<const float4*>(g_qkv + (size_t)head * S_LEN * DK);
#pragma unroll
    for (int i = threadIdx.x; i < 2048; i += 128) {
        float4 v = Kg4[i];
        int r  = i >> 1;                 // source row
        int dh = (i & 1) << 2;           // d base: 0 or 4
        int pr = r >> 1;                 // pair index
        int ln = r & 1;                  // lane within pair
        float* dst = sK + ((pr << 3) + dh) * 2 + ln;
        dst[0] = v.x; dst[2] = v.y; dst[4] = v.z; dst[6] = v.w;
    }
    __syncthreads();

    int q  = qt * 128 + threadIdx.x;
    int pq = q >> 1;
    int lq = q & 1;
    const float scale = 0.35355339059327373f * 1.4426950408889634f; // log2e/sqrt8

    ull q2[8];
#pragma unroll
    for (int d = 0; d < 8; d++) {
        float qa = sK[((pq << 3) + d) * 2 + lq] * scale;
        q2[d] = pack2(qa, qa);
    }

    ull t0 = 0, t1 = 0, t2 = 0, t3 = 0, t4 = 0, t5 = 0, t6 = 0, t7 = 0;
    ull l2 = 0;

    const ulonglong2* Ks = reinterpret_cast<const ulonglong2*>(sK);
#pragma unroll 2
    for (int j = 0; j < S_LEN / 2; j++) {
        ulonglong2 e0 = Ks[j * 4 + 0];
        ulonglong2 e1 = Ks[j * 4 + 1];
        ulonglong2 e2 = Ks[j * 4 + 2];
        ulonglong2 e3 = Ks[j * 4 + 3];

        ull d2 = mul2(q2[0], e0.x);
        d2 = fma2(q2[1], e0.y, d2);
        d2 = fma2(q2[2], e1.x, d2);
        d2 = fma2(q2[3], e1.y, d2);
        d2 = fma2(q2[4], e2.x, d2);
        d2 = fma2(q2[5], e2.y, d2);
        d2 = fma2(q2[6], e3.x, d2);
        d2 = fma2(q2[7], e3.y, d2);

        float s0, s1;
        unpack2(d2, s0, s1);
        float p0 = ex2(s0);
        float p1 = ex2(s1);
        ull p01 = pack2(p0, p1);

        l2 = add2(l2, p01);
        t0 = fma2(p01, e0.x, t0);
        t1 = fma2(p01, e0.y, t1);
        t2 = fma2(p01, e1.x, t2);
        t3 = fma2(p01, e1.y, t3);
        t4 = fma2(p01, e2.x, t4);
        t5 = fma2(p01, e2.y, t5);
        t6 = fma2(p01, e3.x, t6);
        t7 = fma2(p01, e3.y, t7);
    }

    float llo, lhi;
    unpack2(l2, llo, lhi);
    float rl = 1.0f / (llo + lhi);

    float a, b2;
    float o[8];
    unpack2(t0, a, b2); o[0] = (a + b2) * rl;
    unpack2(t1, a, b2); o[1] = (a + b2) * rl;
    unpack2(t2, a, b2); o[2] = (a + b2) * rl;
    unpack2(t3, a, b2); o[3] = (a + b2) * rl;
    unpack2(t4, a, b2); o[4] = (a + b2) * rl;
    unpack2(t5, a, b2); o[5] = (a + b2) * rl;
    unpack2(t6, a, b2); o[6] = (a + b2) * rl;
    unpack2(t7, a, b2); o[7] = (a + b2) * rl;

    int b = head >> 4;
    int h = head & 15;
    float4* o4 = reinterpret_cast<float4*>(
        g_attn + ((size_t)((b << 10) + q) * E_DIM) + h * DK);
    o4[0] = make_float4(o[0], o[1], o[2], o[3]);
    o4[1] = make_float4(o[4], o[5], o[6], o[7]);
}

// ---------------------------------------------------------------------------
// Kernel 3a: transpose combine_w (coalesced reads in combine)
// ---------------------------------------------------------------------------
__global__ void transpose_w(const float* __restrict__ W) {
    int j = blockIdx.x * blockDim.x + threadIdx.x;
    if (j >= E_DIM * E_DIM) return;
    int f = j >> 7;
    int e = j & 127;
    g_wt[j] = __ldg(W + e * E_DIM + f);
}

// ---------------------------------------------------------------------------
// Kernel 3b: combine. R=4 rows/block, grid=1024 -> occ ~43% (vs 10.8% at
// R=16/grid=256), W reuse 4x, a-loads vectorized (LDS.128 covers 4 f).
// ---------------------------------------------------------------------------
#define CR 4
__global__ __launch_bounds__(128) void combine_kernel(float* __restrict__ out) {
    __shared__ __align__(16) float sa[CR * E_DIM];  // 2 KB
    int row0 = blockIdx.x * CR;
    int t = threadIdx.x;

    // 512 floats = 128 float4: one per thread
    reinterpret_cast<float4*>(sa)[t] =
        reinterpret_cast<const float4*>(g_attn + (size_t)row0 * E_DIM)[t];
    __syncthreads();

    float acc0 = 0.f, acc1 = 0.f, acc2 = 0.f, acc3 = 0.f;
    const float4* sa4 = reinterpret_cast<const float4*>(sa);

#pragma unroll 8
    for (int f = 0; f < E_DIM; f += 4) {
        float w0 = __ldg(g_wt + (f + 0) * E_DIM + t);
        float w1 = __ldg(g_wt + (f + 1) * E_DIM + t);
        float w2 = __ldg(g_wt + (f + 2) * E_DIM + t);
        float w3 = __ldg(g_wt + (f + 3) * E_DIM + t);

        float4 a0 = sa4[0 * 32 + (f >> 2)];   // row0+0, f..f+3 (broadcast)
        float4 a1 = sa4[1 * 32 + (f >> 2)];
        float4 a2 = sa4[2 * 32 + (f >> 2)];
        float4 a3 = sa4[3 * 32 + (f >> 2)];

        acc0 = fmaf(a0.x, w0, acc0); acc0 = fmaf(a0.y, w1, acc0);
        acc0 = fmaf(a0.z, w2, acc0); acc0 = fmaf(a0.w, w3, acc0);
        acc1 = fmaf(a1.x, w0, acc1); acc1 = fmaf(a1.y, w1, acc1);
        acc1 = fmaf(a1.z, w2, acc1); acc1 = fmaf(a1.w, w3, acc1);
        acc2 = fmaf(a2.x, w0, acc2); acc2 = fmaf(a2.y, w1, acc2);
        acc2 = fmaf(a2.z, w2, acc2); acc2 = fmaf(a2.w, w3, acc2);
        acc3 = fmaf(a3.x, w0, acc3); acc3 = fmaf(a3.y, w1, acc3);
        acc3 = fmaf(a3.z, w2, acc3); acc3 = fmaf(a3.w, w3, acc3);
    }

    out[(size_t)(row0 + 0) * E_DIM + t] = acc0;
    out[(size_t)(row0 + 1) * E_DIM + t] = acc1;
    out[(size_t)(row0 + 2) * E_DIM + t] = acc2;
    out[(size_t)(row0 + 3) * E_DIM + t] = acc3;
}

// ---------------------------------------------------------------------------
extern "C" void kernel_launch(void* const* d_in, const int* in_sizes, int n_in,
                              void* d_out, int out_size) {
    const float* x  = nullptr;
    const float* rx = nullptr;
    const float* cw = nullptr;
    for (int i = 0; i < n_in; i++) {
        if (in_sizes[i] == NROWS * DK)          x  = (const float*)d_in[i];
        else if (in_sizes[i] == DK)             rx = (const float*)d_in[i];
        else if (in_sizes[i] == E_DIM * E_DIM)  cw = (const float*)d_in[i];
    }
    if (!x)  x  = (const float*)d_in[0];
    if (!rx) rx = (const float*)d_in[1];
    if (!cw) cw = (const float*)d_in[2];

    float* out = (float*)d_out;

    qkv_kernel<<<NROWS / 256, 256>>>(x, rx);
    transpose_w<<<(E_DIM * E_DIM + 255) / 256, 256>>>(cw);
    attn_kernel<<<NHEADS * 8, 128>>>();
    combine_kernel<<<NROWS_E / CR, 128>>>(out);
}

// round 5
// speedup vs baseline: 1.4721x; 1.2011x over previous
#include <cuda_runtime.h>
#include <cuda_bf16.h>
#include <math.h>

// ---------------------------------------------------------------------------
// QuantumAttention, analytic circuit collapse:
//   z_i = cos(x_i + p_i); proj[0] = z1..z7 ; proj[w>=1] = z0..zw
// attention (64 heads, S=1024, d=8) via tf32 mma.sync for QK^T, MUFU ex2
// softmax (no max needed, |s|<=2.83), scalar packed-f32x2 PV; then X @ W^T.
// ---------------------------------------------------------------------------

#define NROWS   65536
#define S_LEN   1024
#define NHEADS  64
#define DK      8
#define E_DIM   128
#define NROWS_E 4096

__device__ float g_qkv[NROWS * DK];       // [b,h,s,d] head-major
__device__ float g_attn[NROWS_E * E_DIM]; // [b,s,e]
__device__ float g_wt[E_DIM * E_DIM];     // Wt[f*128+e] = W[e*128+f]

typedef unsigned long long ull;

__device__ __forceinline__ ull fma2(ull a, ull b, ull c) {
    ull d; asm("fma.rn.f32x2 %0, %1, %2, %3;" : "=l"(d) : "l"(a), "l"(b), "l"(c));
    return d;
}
__device__ __forceinline__ ull add2(ull a, ull b) {
    ull d; asm("add.rn.f32x2 %0, %1, %2;" : "=l"(d) : "l"(a), "l"(b));
    return d;
}
__device__ __forceinline__ ull pack2(float x, float y) {
    ull r; asm("mov.b64 %0, {%1, %2};" : "=l"(r) : "f"(x), "f"(y));
    return r;
}
__device__ __forceinline__ void unpack2(ull v, float& x, float& y) {
    asm("mov.b64 {%0, %1}, %2;" : "=f"(x), "=f"(y) : "l"(v));
}
__device__ __forceinline__ float ex2(float x) {
    float y; asm("ex2.approx.ftz.f32 %0, %1;" : "=f"(y) : "f"(x));
    return y;
}
__device__ __forceinline__ unsigned tf32_of(float f) {
    unsigned u; asm("cvt.rna.tf32.f32 %0, %1;" : "=r"(u) : "f"(f));
    return u;
}
// D = A(16x8) * B(8x8) ; tf32 inputs, f32 accum, C = 0
__device__ __forceinline__ void mma8(float& c0, float& c1, float& c2, float& c3,
                                     unsigned a0, unsigned a1, unsigned a2, unsigned a3,
                                     unsigned b0, unsigned b1) {
    asm("mma.sync.aligned.m16n8k8.row.col.f32.tf32.tf32.f32 "
        "{%0,%1,%2,%3},{%4,%5,%6,%7},{%8,%9},{%10,%11,%12,%13};"
        : "=f"(c0), "=f"(c1), "=f"(c2), "=f"(c3)
        : "r"(a0), "r"(a1), "r"(a2), "r"(a3), "r"(b0), "r"(b1),
          "f"(0.f), "f"(0.f), "f"(0.f), "f"(0.f));
}

// ---------------------------------------------------------------------------
// Kernel 1: quantum projection
// ---------------------------------------------------------------------------
__global__ void qkv_kernel(const float* __restrict__ x,
                           const float* __restrict__ rx) {
    int r = blockIdx.x * blockDim.x + threadIdx.x;
    if (r >= NROWS) return;

    float pv[8];
#pragma unroll
    for (int i = 0; i < 8; i++) pv[i] = __ldg(rx + i);

    const float4* xr = reinterpret_cast<const float4*>(x + (size_t)r * DK);
    float4 x0 = xr[0];
    float4 x1 = xr[1];

    float z0 = __cosf(x0.x + pv[0]);
    float z1 = __cosf(x0.y + pv[1]);
    float z2 = __cosf(x0.z + pv[2]);
    float z3 = __cosf(x0.w + pv[3]);
    float z4 = __cosf(x1.x + pv[4]);
    float z5 = __cosf(x1.y + pv[5]);
    float z6 = __cosf(x1.z + pv[6]);
    float z7 = __cosf(x1.w + pv[7]);

    float o1 = z0 * z1;
    float o2 = o1 * z2;
    float o3 = o2 * z3;
    float o4 = o3 * z4;
    float o5 = o4 * z5;
    float o6 = o5 * z6;
    float o7 = o6 * z7;
    float o0 = z1 * z2;
    o0 *= z3; o0 *= z4; o0 *= z5; o0 *= z6; o0 *= z7;

    int h  = r & 15;
    int bs = r >> 4;
    int bb = bs >> 10;
    int s  = bs & 1023;
    int dst = ((bb << 4) + h) * S_LEN + s;

    float4* out = reinterpret_cast<float4*>(g_qkv + (size_t)dst * DK);
    out[0] = make_float4(o0, o1, o2, o3);
    out[1] = make_float4(o4, o5, o6, o7);
}

// ---------------------------------------------------------------------------
// Kernel 2: attention. One block = 128 q rows x full 1024 keys of one head.
// Shared buffer sKt holds tf32(K) in pair-interleaved row layout:
//   row r (8 uints): [d0,d4, d1,d5, d2,d6, d3,d7]
// Serves: A-frags (LDS.64 @ 2*t4), B-frags (LDS.64 @ 2*t4), V rows
// (2x LDS.128, words = f32x2 pairs (j, j+4) matching packed accumulators).
// ---------------------------------------------------------------------------
__global__ __launch_bounds__(128) void attn_kernel() {
    __shared__ __align__(16) unsigned sKt[S_LEN * DK];   // 32 KB

    int head = blockIdx.x >> 3;
    int qt   = blockIdx.x & 7;
    int tid  = threadIdx.x;
    int w    = tid >> 5;
    int lane = tid & 31;
    int g    = lane >> 2;
    int t4   = lane & 3;

    // ---- load + tf32-convert head K into interleaved shared layout ----
    const float4* Kg4 = reinterpret_cast<const float4*>(g_qkv + (size_t)head * S_LEN * DK);
#pragma unroll
    for (int i = 0; i < 8; i++) {
        int r = tid + i * 128;
        float4 f0 = Kg4[2 * r];
        float4 f1 = Kg4[2 * r + 1];
        uint4* dst = reinterpret_cast<uint4*>(sKt + r * 8);
        dst[0] = make_uint4(tf32_of(f0.x), tf32_of(f1.x), tf32_of(f0.y), tf32_of(f1.y));
        dst[1] = make_uint4(tf32_of(f0.z), tf32_of(f1.z), tf32_of(f0.w), tf32_of(f1.w));
    }
    __syncthreads();

    const float scale = 0.35355339059327373f * 1.4426950408889634f; // log2e/sqrt8

    // ---- A fragments (scaled): warp covers local q rows [w*32, w*32+32) ----
    int ar = qt * 128 + w * 32 + g;
    uint2 ra0 = *reinterpret_cast<const uint2*>(sKt + (ar     ) * 8 + 2 * t4);
    uint2 ra1 = *reinterpret_cast<const uint2*>(sKt + (ar +  8) * 8 + 2 * t4);
    uint2 ra2 = *reinterpret_cast<const uint2*>(sKt + (ar + 16) * 8 + 2 * t4);
    uint2 ra3 = *reinterpret_cast<const uint2*>(sKt + (ar + 24) * 8 + 2 * t4);
    // tile0: rows g, g+8 ; tile1: rows 16+g, 24+g
    unsigned A0[4], A1[4];
    A0[0] = tf32_of(__uint_as_float(ra0.x) * scale);
    A0[1] = tf32_of(__uint_as_float(ra1.x) * scale);
    A0[2] = tf32_of(__uint_as_float(ra0.y) * scale);
    A0[3] = tf32_of(__uint_as_float(ra1.y) * scale);
    A1[0] = tf32_of(__uint_as_float(ra2.x) * scale);
    A1[1] = tf32_of(__uint_as_float(ra3.x) * scale);
    A1[2] = tf32_of(__uint_as_float(ra2.y) * scale);
    A1[3] = tf32_of(__uint_as_float(ra3.y) * scale);

    // accumulators: 4 q-rows (g, g+8, 16+g, 24+g), 4 f32x2 pairs (j, j+4)
    ull ac[4][4];
#pragma unroll
    for (int r = 0; r < 4; r++)
#pragma unroll
        for (int j = 0; j < 4; j++) ac[r][j] = 0ull;
    ull lac[4] = {0ull, 0ull, 0ull, 0ull};

#pragma unroll 2
    for (int kb = 0; kb < S_LEN; kb += 8) {
        uint2 bb = *reinterpret_cast<const uint2*>(sKt + (kb + g) * 8 + 2 * t4);

        float c0, c1, c2, c3, d0, d1, d2, d3;
        mma8(c0, c1, c2, c3, A0[0], A0[1], A0[2], A0[3], bb.x, bb.y);
        mma8(d0, d1, d2, d3, A1[0], A1[1], A1[2], A1[3], bb.x, bb.y);

        // V rows for this thread's score columns: kb+2*t4, kb+2*t4+1
        const ulonglong2* v0p = reinterpret_cast<const ulonglong2*>(sKt + (kb + 2 * t4) * 8);
        const ulonglong2* v1p = reinterpret_cast<const ulonglong2*>(sKt + (kb + 2 * t4 + 1) * 8);
        ulonglong2 va = v0p[0], vb = v0p[1];   // row r0 pairs (0,4),(1,5) | (2,6),(3,7)
        ulonglong2 vc = v1p[0], vd = v1p[1];   // row r1

        float p0 = ex2(c0), p1 = ex2(c1), p2 = ex2(c2), p3 = ex2(c3);
        float e0 = ex2(d0), e1 = ex2(d1), e2 = ex2(d2), e3 = ex2(d3);

        ull pp;
        // row g: scores p0 (col r0), p1 (col r1)
        pp = pack2(p0, p0);
        ac[0][0] = fma2(pp, va.x, ac[0][0]); ac[0][1] = fma2(pp, va.y, ac[0][1]);
        ac[0][2] = fma2(pp, vb.x, ac[0][2]); ac[0][3] = fma2(pp, vb.y, ac[0][3]);
        pp = pack2(p1, p1);
        ac[0][0] = fma2(pp, vc.x, ac[0][0]); ac[0][1] = fma2(pp, vc.y, ac[0][1]);
        ac[0][2] = fma2(pp, vd.x, ac[0][2]); ac[0][3] = fma2(pp, vd.y, ac[0][3]);
        lac[0] = add2(lac[0], pack2(p0, p1));
        // row g+8: p2, p3
        pp = pack2(p2, p2);
        ac[1][0] = fma2(pp, va.x, ac[1][0]); ac[1][1] = fma2(pp, va.y, ac[1][1]);
        ac[1][2] = fma2(pp, vb.x, ac[1][2]); ac[1][3] = fma2(pp, vb.y, ac[1][3]);
        pp = pack2(p3, p3);
        ac[1][0] = fma2(pp, vc.x, ac[1][0]); ac[1][1] = fma2(pp, vc.y, ac[1][1]);
        ac[1][2] = fma2(pp, vd.x, ac[1][2]); ac[1][3] = fma2(pp, vd.y, ac[1][3]);
        lac[1] = add2(lac[1], pack2(p2, p3));
        // row 16+g: e0, e1
        pp = pack2(e0, e0);
        ac[2][0] = fma2(pp, va.x, ac[2][0]); ac[2][1] = fma2(pp, va.y, ac[2][1]);
        ac[2][2] = fma2(pp, vb.x, ac[2][2]); ac[2][3] = fma2(pp, vb.y, ac[2][3]);
        pp = pack2(e1, e1);
        ac[2][0] = fma2(pp, vc.x, ac[2][0]); ac[2][1] = fma2(pp, vc.y, ac[2][1]);
        ac[2][2] = fma2(pp, vd.x, ac[2][2]); ac[2][3] = fma2(pp, vd.y, ac[2][3]);
        lac[2] = add2(lac[2], pack2(e0, e1));
        // row 24+g: e2, e3
        pp = pack2(e2, e2);
        ac[3][0] = fma2(pp, va.x, ac[3][0]); ac[3][1] = fma2(pp, va.y, ac[3][1]);
        ac[3][2] = fma2(pp, vb.x, ac[3][2]); ac[3][3] = fma2(pp, vb.y, ac[3][3]);
        pp = pack2(e3, e3);
        ac[3][0] = fma2(pp, vc.x, ac[3][0]); ac[3][1] = fma2(pp, vc.y, ac[3][1]);
        ac[3][2] = fma2(pp, vd.x, ac[3][2]); ac[3][3] = fma2(pp, vd.y, ac[3][3]);
        lac[3] = add2(lac[3], pack2(e2, e3));
    }

    // ---- epilogue: reduce partial column-sums across the 4 lanes of each group
    int bb_ = head >> 4;
    int hh  = head & 15;
#pragma unroll
    for (int r = 0; r < 4; r++) {
        float o[8];
#pragma unroll
        for (int j = 0; j < 4; j++) unpack2(ac[r][j], o[j], o[j + 4]);
        float llo, lhi;
        unpack2(lac[r], llo, lhi);
        float l = llo + lhi;
#pragma unroll
        for (int d = 0; d < 8; d++) {
            o[d] += __shfl_xor_sync(0xffffffffu, o[d], 1);
            o[d] += __shfl_xor_sync(0xffffffffu, o[d], 2);
        }
        l += __shfl_xor_sync(0xffffffffu, l, 1);
        l += __shfl_xor_sync(0xffffffffu, l, 2);

        if (t4 == 0) {
            float rl = 1.0f / l;
            int qrow = qt * 128 + w * 32 + g + 8 * r;      // head-local s index
            float4* o4 = reinterpret_cast<float4*>(
                g_attn + ((size_t)((bb_ << 10) + qrow) * E_DIM) + hh * DK);
            o4[0] = make_float4(o[0] * rl, o[1] * rl, o[2] * rl, o[3] * rl);
            o4[1] = make_float4(o[4] * rl, o[5] * rl, o[6] * rl, o[7] * rl);
        }
    }
}

// ---------------------------------------------------------------------------
// Kernel 3a: transpose combine_w
// ---------------------------------------------------------------------------
__global__ void transpose_w(const float* __restrict__ W) {
    int j = blockIdx.x * blockDim.x + threadIdx.x;
    if (j >= E_DIM * E_DIM) return;
    int f = j >> 7;
    int e = j & 127;
    g_wt[j] = __ldg(W + e * E_DIM + f);
}

// ---------------------------------------------------------------------------
// Kernel 3b: combine, f-split: 256 threads, halves cover f in [0,64)/[64,128),
// smem reduction. grid 1024 -> 56 warps/SM.
// ---------------------------------------------------------------------------
#define CR 4
__global__ __launch_bounds__(256) void combine_kernel(float* __restrict__ out) {
    __shared__ __align__(16) float sa[CR * E_DIM];   // 2 KB
    __shared__ float red[CR * E_DIM];                 // 2 KB
    int row0 = blockIdx.x * CR;
    int t = threadIdx.x;
    int e = t & 127;
    int half = t >> 7;

    if (t < 128)
        reinterpret_cast<float4*>(sa)[t] =
            reinterpret_cast<const float4*>(g_attn + (size_t)row0 * E_DIM)[t];
    __syncthreads();

    float acc0 = 0.f, acc1 = 0.f, acc2 = 0.f, acc3 = 0.f;
    const float4* sa4 = reinterpret_cast<const float4*>(sa);
    int fb = half * 64;

#pragma unroll 4
    for (int f = fb; f < fb + 64; f += 4) {
        float w0 = __ldg(g_wt + (f + 0) * E_DIM + e);
        float w1 = __ldg(g_wt + (f + 1) * E_DIM + e);
        float w2 = __ldg(g_wt + (f + 2) * E_DIM + e);
        float w3 = __ldg(g_wt + (f + 3) * E_DIM + e);

        float4 a0 = sa4[0 * 32 + (f >> 2)];
        float4 a1 = sa4[1 * 32 + (f >> 2)];
        float4 a2 = sa4[2 * 32 + (f >> 2)];
        float4 a3 = sa4[3 * 32 + (f >> 2)];

        acc0 = fmaf(a0.x, w0, acc0); acc0 = fmaf(a0.y, w1, acc0);
        acc0 = fmaf(a0.z, w2, acc0); acc0 = fmaf(a0.w, w3, acc0);
        acc1 = fmaf(a1.x, w0, acc1); acc1 = fmaf(a1.y, w1, acc1);
        acc1 = fmaf(a1.z, w2, acc1); acc1 = fmaf(a1.w, w3, acc1);
        acc2 = fmaf(a2.x, w0, acc2); acc2 = fmaf(a2.y, w1, acc2);
        acc2 = fmaf(a2.z, w2, acc2); acc2 = fmaf(a2.w, w3, acc2);
        acc3 = fmaf(a3.x, w0, acc3); acc3 = fmaf(a3.y, w1, acc3);
        acc3 = fmaf(a3.z, w2, acc3); acc3 = fmaf(a3.w, w3, acc3);
    }

    if (half) {
        red[0 * E_DIM + e] = acc0;
        red[1 * E_DIM + e] = acc1;
        red[2 * E_DIM + e] = acc2;
        red[3 * E_DIM + e] = acc3;
    }
    __syncthreads();
    if (!half) {
        out[(size_t)(row0 + 0) * E_DIM + e] = acc0 + red[0 * E_DIM + e];
        out[(size_t)(row0 + 1) * E_DIM + e] = acc1 + red[1 * E_DIM + e];
        out[(size_t)(row0 + 2) * E_DIM + e] = acc2 + red[2 * E_DIM + e];
        out[(size_t)(row0 + 3) * E_DIM + e] = acc3 + red[3 * E_DIM + e];
    }
}

// ---------------------------------------------------------------------------
extern "C" void kernel_launch(void* const* d_in, const int* in_sizes, int n_in,
                              void* d_out, int out_size) {
    const float* x  = nullptr;
    const float* rx = nullptr;
    const float* cw = nullptr;
    for (int i = 0; i < n_in; i++) {
        if (in_sizes[i] == NROWS * DK)          x  = (const float*)d_in[i];
        else if (in_sizes[i] == DK)             rx = (const float*)d_in[i];
        else if (in_sizes[i] == E_DIM * E_DIM)  cw = (const float*)d_in[i];
    }
    if (!x)  x  = (const float*)d_in[0];
    if (!rx) rx = (const float*)d_in[1];
    if (!cw) cw = (const float*)d_in[2];

    float* out = (float*)d_out;

    qkv_kernel<<<NROWS / 256, 256>>>(x, rx);
    transpose_w<<<(E_DIM * E_DIM + 255) / 256, 256>>>(cw);
    attn_kernel<<<NHEADS * 8, 128>>>();
    combine_kernel<<<NROWS_E / CR, 256>>>(out);
}

// round 7
// speedup vs baseline: 1.9993x; 1.3581x over previous
#include <cuda_runtime.h>
#include <cuda_bf16.h>
#include <math.h>

// ---------------------------------------------------------------------------
// QuantumAttention, analytic circuit collapse:
//   z_i = cos(x_i + p_i); proj[0] = z1..z7 ; proj[w>=1] = z0..zw
// Attention fully on tensor pipe: QK^T via tf32 mma, ex2 softmax (no max,
// |s|<=2.83), P@V ALSO via tf32 mma using the thread's own V pair as the
// B fragment so the QK C-layout feeds the PV A-layout with a zero-cost
// register remap (p0,p2,p1,p3). Then X @ W^T.
// ---------------------------------------------------------------------------

#define NROWS   65536
#define S_LEN   1024
#define NHEADS  64
#define DK      8
#define E_DIM   128
#define NROWS_E 4096

__device__ float g_qkv[NROWS * DK];       // [b,h,s,d] head-major
__device__ float g_attn[NROWS_E * E_DIM]; // [b,s,e]
__device__ float g_wt[E_DIM * E_DIM];     // Wt[f*128+e] = W[e*128+f]

typedef unsigned long long ull;

__device__ __forceinline__ ull add2(ull a, ull b) {
    ull d; asm("add.rn.f32x2 %0, %1, %2;" : "=l"(d) : "l"(a), "l"(b));
    return d;
}
__device__ __forceinline__ ull pack2(float x, float y) {
    ull r; asm("mov.b64 %0, {%1, %2};" : "=l"(r) : "f"(x), "f"(y));
    return r;
}
__device__ __forceinline__ void unpack2(ull v, float& x, float& y) {
    asm("mov.b64 {%0, %1}, %2;" : "=f"(x), "=f"(y) : "l"(v));
}
__device__ __forceinline__ float ex2(float x) {
    float y; asm("ex2.approx.ftz.f32 %0, %1;" : "=f"(y) : "f"(x));
    return y;
}
__device__ __forceinline__ unsigned tf32_of(float f) {
    unsigned u; asm("cvt.rna.tf32.f32 %0, %1;" : "=r"(u) : "f"(f));
    return u;
}
// D = A*B (C=0)
__device__ __forceinline__ void mma8(float& c0, float& c1, float& c2, float& c3,
                                     unsigned a0, unsigned a1, unsigned a2, unsigned a3,
                                     unsigned b0, unsigned b1) {
    asm("mma.sync.aligned.m16n8k8.row.col.f32.tf32.tf32.f32 "
        "{%0,%1,%2,%3},{%4,%5,%6,%7},{%8,%9},{%10,%11,%12,%13};"
        : "=f"(c0), "=f"(c1), "=f"(c2), "=f"(c3)
        : "r"(a0), "r"(a1), "r"(a2), "r"(a3), "r"(b0), "r"(b1),
          "f"(0.f), "f"(0.f), "f"(0.f), "f"(0.f));
}
// C += A*B (accumulating)
__device__ __forceinline__ void mma8_acc(float& c0, float& c1, float& c2, float& c3,
                                         unsigned a0, unsigned a1, unsigned a2, unsigned a3,
                                         unsigned b0, unsigned b1) {
    asm("mma.sync.aligned.m16n8k8.row.col.f32.tf32.tf32.f32 "
        "{%0,%1,%2,%3},{%4,%5,%6,%7},{%8,%9},{%0,%1,%2,%3};"
        : "+f"(c0), "+f"(c1), "+f"(c2), "+f"(c3)
        : "r"(a0), "r"(a1), "r"(a2), "r"(a3), "r"(b0), "r"(b1));
}

// ---------------------------------------------------------------------------
// Kernel 1: quantum projection
// ---------------------------------------------------------------------------
__global__ void qkv_kernel(const float* __restrict__ x,
                           const float* __restrict__ rx) {
    int r = blockIdx.x * blockDim.x + threadIdx.x;
    if (r >= NROWS) return;

    float pv[8];
#pragma unroll
    for (int i = 0; i < 8; i++) pv[i] = __ldg(rx + i);

    const float4* xr = reinterpret_cast<const float4*>(x + (size_t)r * DK);
    float4 x0 = xr[0];
    float4 x1 = xr[1];

    float z0 = __cosf(x0.x + pv[0]);
    float z1 = __cosf(x0.y + pv[1]);
    float z2 = __cosf(x0.z + pv[2]);
    float z3 = __cosf(x0.w + pv[3]);
    float z4 = __cosf(x1.x + pv[4]);
    float z5 = __cosf(x1.y + pv[5]);
    float z6 = __cosf(x1.z + pv[6]);
    float z7 = __cosf(x1.w + pv[7]);

    float o1 = z0 * z1;
    float o2 = o1 * z2;
    float o3 = o2 * z3;
    float o4 = o3 * z4;
    float o5 = o4 * z5;
    float o6 = o5 * z6;
    float o7 = o6 * z7;
    float o0 = z1 * z2;
    o0 *= z3; o0 *= z4; o0 *= z5; o0 *= z6; o0 *= z7;

    int h  = r & 15;
    int bs = r >> 4;
    int bb = bs >> 10;
    int s  = bs & 1023;
    int dst = ((bb << 4) + h) * S_LEN + s;

    float4* out = reinterpret_cast<float4*>(g_qkv + (size_t)dst * DK);
    out[0] = make_float4(o0, o1, o2, o3);
    out[1] = make_float4(o4, o5, o6, o7);
}

// ---------------------------------------------------------------------------
// Kernel 2: attention. One block = 128 q rows x all 1024 keys of one head.
// sKt row r (8 uints, tf32): [d0,d4, d1,d5, d2,d6, d3,d7].
//   QK B-frag: uint2 @ (kb+g)*8 + 2*t4 -> (K[kb+g][t4], K[kb+g][t4+4])
//   PV: this thread's B-frag regs are V[kb+2*t4][g], V[kb+2*t4+1][g];
//   the matching A-frag is (p0, p2, p1, p3) — pure register reorder.
// ---------------------------------------------------------------------------
__global__ __launch_bounds__(128) void attn_kernel() {
    __shared__ __align__(16) unsigned sKt[S_LEN * DK];   // 32 KB

    int head = blockIdx.x >> 3;
    int qt   = blockIdx.x & 7;
    int tid  = threadIdx.x;
    int w    = tid >> 5;
    int lane = tid & 31;
    int g    = lane >> 2;
    int t4   = lane & 3;

    // ---- load + tf32-convert head K/V into interleaved shared layout ----
    const float4* Kg4 = reinterpret_cast<const float4*>(g_qkv + (size_t)head * S_LEN * DK);
#pragma unroll
    for (int i = 0; i < 8; i++) {
        int r = tid + i * 128;
        float4 f0 = Kg4[2 * r];
        float4 f1 = Kg4[2 * r + 1];
        uint4* dst = reinterpret_cast<uint4*>(sKt + r * 8);
        dst[0] = make_uint4(tf32_of(f0.x), tf32_of(f1.x), tf32_of(f0.y), tf32_of(f1.y));
        dst[1] = make_uint4(tf32_of(f0.z), tf32_of(f1.z), tf32_of(f0.w), tf32_of(f1.w));
    }
    __syncthreads();

    const float scale = 0.35355339059327373f * 1.4426950408889634f; // log2e/sqrt8

    // ---- Q fragments (scaled): warp covers local q rows [w*32, w*32+32) ----
    int ar = qt * 128 + w * 32 + g;
    uint2 ra0 = *reinterpret_cast<const uint2*>(sKt + (ar     ) * 8 + 2 * t4);
    uint2 ra1 = *reinterpret_cast<const uint2*>(sKt + (ar +  8) * 8 + 2 * t4);
    uint2 ra2 = *reinterpret_cast<const uint2*>(sKt + (ar + 16) * 8 + 2 * t4);
    uint2 ra3 = *reinterpret_cast<const uint2*>(sKt + (ar + 24) * 8 + 2 * t4);
    unsigned A0[4], A1[4];
    A0[0] = tf32_of(__uint_as_float(ra0.x) * scale);
    A0[1] = tf32_of(__uint_as_float(ra1.x) * scale);
    A0[2] = tf32_of(__uint_as_float(ra0.y) * scale);
    A0[3] = tf32_of(__uint_as_float(ra1.y) * scale);
    A1[0] = tf32_of(__uint_as_float(ra2.x) * scale);
    A1[1] = tf32_of(__uint_as_float(ra3.x) * scale);
    A1[2] = tf32_of(__uint_as_float(ra2.y) * scale);
    A1[3] = tf32_of(__uint_as_float(ra3.y) * scale);

    // PV output accumulators (stay in mma C regs across all chunks)
    float oc0 = 0.f, oc1 = 0.f, oc2 = 0.f, oc3 = 0.f;   // rows g, g+8
    float od0 = 0.f, od1 = 0.f, od2 = 0.f, od3 = 0.f;   // rows 16+g, 24+g
    ull lac01 = 0ull, lac23 = 0ull;                     // softmax denominators

    // V B-frag source index inside a row (dim g position in interleaved row)
    int vidx = (g < 4) ? (2 * g) : (2 * (g - 4) + 1);
    const unsigned* vrow = sKt + vidx;

#pragma unroll 2
    for (int kb = 0; kb < S_LEN; kb += 8) {
        uint2 bb = *reinterpret_cast<const uint2*>(sKt + (kb + g) * 8 + 2 * t4);

        float c0, c1, c2, c3, d0, d1, d2, d3;
        mma8(c0, c1, c2, c3, A0[0], A0[1], A0[2], A0[3], bb.x, bb.y);
        mma8(d0, d1, d2, d3, A1[0], A1[1], A1[2], A1[3], bb.x, bb.y);

        float p0 = ex2(c0), p1 = ex2(c1), p2 = ex2(c2), p3 = ex2(c3);
        float e0 = ex2(d0), e1 = ex2(d1), e2 = ex2(d2), e3 = ex2(d3);

        // V fragment: keys kb+2*t4, kb+2*t4+1 ; dim g (already tf32)
        unsigned vb0 = vrow[(kb + 2 * t4) * 8];
        unsigned vb1 = vrow[(kb + 2 * t4 + 1) * 8];

        mma8_acc(oc0, oc1, oc2, oc3,
                 tf32_of(p0), tf32_of(p2), tf32_of(p1), tf32_of(p3), vb0, vb1);
        mma8_acc(od0, od1, od2, od3,
                 tf32_of(e0), tf32_of(e2), tf32_of(e1), tf32_of(e3), vb0, vb1);

        lac01 = add2(lac01, add2(pack2(p0, p2), pack2(p1, p3)));
        lac23 = add2(lac23, add2(pack2(e0, e2), pack2(e1, e3)));
    }

    // ---- epilogue: O complete per thread (mma reduced over k). Reduce l
    // across the 4 lanes of each group, then scaled float2 stores.
    float lg, lg8, l16, l24;
    unpack2(lac01, lg, lg8);
    unpack2(lac23, l16, l24);
    lg  += __shfl_xor_sync(0xffffffffu, lg, 1);  lg  += __shfl_xor_sync(0xffffffffu, lg, 2);
    lg8 += __shfl_xor_sync(0xffffffffu, lg8, 1); lg8 += __shfl_xor_sync(0xffffffffu, lg8, 2);
    l16 += __shfl_xor_sync(0xffffffffu, l16, 1); l16 += __shfl_xor_sync(0xffffffffu, l16, 2);
    l24 += __shfl_xor_sync(0xffffffffu, l24, 1); l24 += __shfl_xor_sync(0xffffffffu, l24, 2);

    float r0 = 1.0f / lg, r1 = 1.0f / lg8, r2 = 1.0f / l16, r3 = 1.0f / l24;

    int bb_ = head >> 4;
    int hh  = head & 15;
    int row = qt * 128 + w * 32 + g;
    size_t base = (size_t)((bb_ << 10) + row) * E_DIM + hh * DK + 2 * t4;

    *reinterpret_cast<float2*>(g_attn + base)                = make_float2(oc0 * r0, oc1 * r0);
    *reinterpret_cast<float2*>(g_attn + base +  8 * E_DIM)   = make_float2(oc2 * r1, oc3 * r1);
    *reinterpret_cast<float2*>(g_attn + base + 16 * E_DIM)   = make_float2(od0 * r2, od1 * r2);
    *reinterpret_cast<float2*>(g_attn + base + 24 * E_DIM)   = make_float2(od2 * r3, od3 * r3);
}

// ---------------------------------------------------------------------------
// Kernel 3a: transpose combine_w
// ---------------------------------------------------------------------------
__global__ void transpose_w(const float* __restrict__ W) {
    int j = blockIdx.x * blockDim.x + threadIdx.x;
    if (j >= E_DIM * E_DIM) return;
    int f = j >> 7;
    int e = j & 127;
    g_wt[j] = __ldg(W + e * E_DIM + f);
}

// ---------------------------------------------------------------------------
// Kernel 3b: combine (unchanged for clean attribution)
// ---------------------------------------------------------------------------
#define CR 4
__global__ __launch_bounds__(256) void combine_kernel(float* __restrict__ out) {
    __shared__ __align__(16) float sa[CR * E_DIM];
    __shared__ float red[CR * E_DIM];
    int row0 = blockIdx.x * CR;
    int t = threadIdx.x;
    int e = t & 127;
    int half = t >> 7;

    if (t < 128)
        reinterpret_cast<float4*>(sa)[t] =
            reinterpret_cast<const float4*>(g_attn + (size_t)row0 * E_DIM)[t];
    __syncthreads();

    float acc0 = 0.f, acc1 = 0.f, acc2 = 0.f, acc3 = 0.f;
    const float4* sa4 = reinterpret_cast<const float4*>(sa);
    int fb = half * 64;

#pragma unroll 4
    for (int f = fb; f < fb + 64; f += 4) {
        float w0 = __ldg(g_wt + (f + 0) * E_DIM + e);
        float w1 = __ldg(g_wt + (f + 1) * E_DIM + e);
        float w2 = __ldg(g_wt + (f + 2) * E_DIM + e);
        float w3 = __ldg(g_wt + (f + 3) * E_DIM + e);

        float4 a0 = sa4[0 * 32 + (f >> 2)];
        float4 a1 = sa4[1 * 32 + (f >> 2)];
        float4 a2 = sa4[2 * 32 + (f >> 2)];
        float4 a3 = sa4[3 * 32 + (f >> 2)];

        acc0 = fmaf(a0.x, w0, acc0); acc0 = fmaf(a0.y, w1, acc0);
        acc0 = fmaf(a0.z, w2, acc0); acc0 = fmaf(a0.w, w3, acc0);
        acc1 = fmaf(a1.x, w0, acc1); acc1 = fmaf(a1.y, w1, acc1);
        acc1 = fmaf(a1.z, w2, acc1); acc1 = fmaf(a1.w, w3, acc1);
        acc2 = fmaf(a2.x, w0, acc2); acc2 = fmaf(a2.y, w1, acc2);
        acc2 = fmaf(a2.z, w2, acc2); acc2 = fmaf(a2.w, w3, acc2);
        acc3 = fmaf(a3.x, w0, acc3); acc3 = fmaf(a3.y, w1, acc3);
        acc3 = fmaf(a3.z, w2, acc3); acc3 = fmaf(a3.w, w3, acc3);
    }

    if (half) {
        red[0 * E_DIM + e] = acc0;
        red[1 * E_DIM + e] = acc1;
        red[2 * E_DIM + e] = acc2;
        red[3 * E_DIM + e] = acc3;
    }
    __syncthreads();
    if (!half) {
        out[(size_t)(row0 + 0) * E_DIM + e] = acc0 + red[0 * E_DIM + e];
        out[(size_t)(row0 + 1) * E_DIM + e] = acc1 + red[1 * E_DIM + e];
        out[(size_t)(row0 + 2) * E_DIM + e] = acc2 + red[2 * E_DIM + e];
        out[(size_t)(row0 + 3) * E_DIM + e] = acc3 + red[3 * E_DIM + e];
    }
}

// ---------------------------------------------------------------------------
extern "C" void kernel_launch(void* const* d_in, const int* in_sizes, int n_in,
                              void* d_out, int out_size) {
    const float* x  = nullptr;
    const float* rx = nullptr;
    const float* cw = nullptr;
    for (int i = 0; i < n_in; i++) {
        if (in_sizes[i] == NROWS * DK)          x  = (const float*)d_in[i];
        else if (in_sizes[i] == DK)             rx = (const float*)d_in[i];
        else if (in_sizes[i] == E_DIM * E_DIM)  cw = (const float*)d_in[i];
    }
    if (!x)  x  = (const float*)d_in[0];
    if (!rx) rx = (const float*)d_in[1];
    if (!cw) cw = (const float*)d_in[2];

    float* out = (float*)d_out;

    qkv_kernel<<<NROWS / 256, 256>>>(x, rx);
    transpose_w<<<(E_DIM * E_DIM + 255) / 256, 256>>>(cw);
    attn_kernel<<<NHEADS * 8, 128>>>();
    combine_kernel<<<NROWS_E / CR, 256>>>(out);
}

// round 8
// speedup vs baseline: 2.2070x; 1.1039x over previous
#include <cuda_runtime.h>
#include <cuda_bf16.h>
#include <math.h>

// ---------------------------------------------------------------------------
// QuantumAttention, analytic circuit collapse:
//   z_i = cos(x_i + p_i); proj[0] = z1..z7 ; proj[w>=1] = z0..zw
// Attention on tensor pipe (tf32 mma QK^T and P@V with zero-cost fragment
// remap), ex2 softmax (no max needed, |s|<=2.83). Combine GEMM on tensor
// pipe with 3-term tf32 split (hi*hi + hi*lo + lo*hi ~ fp32 accuracy).
// ---------------------------------------------------------------------------

#define NROWS   65536
#define S_LEN   1024
#define NHEADS  64
#define DK      8
#define E_DIM   128
#define NROWS_E 4096

__device__ float g_qkv[NROWS * DK];       // [b,h,s,d] head-major
__device__ float g_attn[NROWS_E * E_DIM]; // [b,s,e]
__device__ uint4 g_wb[16 * 16 * 32];      // W packed as split B-fragments

typedef unsigned long long ull;

__device__ __forceinline__ ull add2(ull a, ull b) {
    ull d; asm("add.rn.f32x2 %0, %1, %2;" : "=l"(d) : "l"(a), "l"(b));
    return d;
}
__device__ __forceinline__ ull pack2(float x, float y) {
    ull r; asm("mov.b64 %0, {%1, %2};" : "=l"(r) : "f"(x), "f"(y));
    return r;
}
__device__ __forceinline__ void unpack2(ull v, float& x, float& y) {
    asm("mov.b64 {%0, %1}, %2;" : "=f"(x), "=f"(y) : "l"(v));
}
__device__ __forceinline__ float ex2(float x) {
    float y; asm("ex2.approx.ftz.f32 %0, %1;" : "=f"(y) : "f"(x));
    return y;
}
__device__ __forceinline__ unsigned tf32_of(float f) {
    unsigned u; asm("cvt.rna.tf32.f32 %0, %1;" : "=r"(u) : "f"(f));
    return u;
}
// D = A*B (C=0)
__device__ __forceinline__ void mma8(float& c0, float& c1, float& c2, float& c3,
                                     unsigned a0, unsigned a1, unsigned a2, unsigned a3,
                                     unsigned b0, unsigned b1) {
    asm("mma.sync.aligned.m16n8k8.row.col.f32.tf32.tf32.f32 "
        "{%0,%1,%2,%3},{%4,%5,%6,%7},{%8,%9},{%10,%11,%12,%13};"
        : "=f"(c0), "=f"(c1), "=f"(c2), "=f"(c3)
        : "r"(a0), "r"(a1), "r"(a2), "r"(a3), "r"(b0), "r"(b1),
          "f"(0.f), "f"(0.f), "f"(0.f), "f"(0.f));
}
// C += A*B
__device__ __forceinline__ void mma8_acc(float& c0, float& c1, float& c2, float& c3,
                                         unsigned a0, unsigned a1, unsigned a2, unsigned a3,
                                         unsigned b0, unsigned b1) {
    asm("mma.sync.aligned.m16n8k8.row.col.f32.tf32.tf32.f32 "
        "{%0,%1,%2,%3},{%4,%5,%6,%7},{%8,%9},{%0,%1,%2,%3};"
        : "+f"(c0), "+f"(c1), "+f"(c2), "+f"(c3)
        : "r"(a0), "r"(a1), "r"(a2), "r"(a3), "r"(b0), "r"(b1));
}

// ---------------------------------------------------------------------------
// Kernel 1: quantum projection
// ---------------------------------------------------------------------------
__global__ void qkv_kernel(const float* __restrict__ x,
                           const float* __restrict__ rx) {
    int r = blockIdx.x * blockDim.x + threadIdx.x;
    if (r >= NROWS) return;

    float pv[8];
#pragma unroll
    for (int i = 0; i < 8; i++) pv[i] = __ldg(rx + i);

    const float4* xr = reinterpret_cast<const float4*>(x + (size_t)r * DK);
    float4 x0 = xr[0];
    float4 x1 = xr[1];

    float z0 = __cosf(x0.x + pv[0]);
    float z1 = __cosf(x0.y + pv[1]);
    float z2 = __cosf(x0.z + pv[2]);
    float z3 = __cosf(x0.w + pv[3]);
    float z4 = __cosf(x1.x + pv[4]);
    float z5 = __cosf(x1.y + pv[5]);
    float z6 = __cosf(x1.z + pv[6]);
    float z7 = __cosf(x1.w + pv[7]);

    float o1 = z0 * z1;
    float o2 = o1 * z2;
    float o3 = o2 * z3;
    float o4 = o3 * z4;
    float o5 = o4 * z5;
    float o6 = o5 * z6;
    float o7 = o6 * z7;
    float o0 = z1 * z2;
    o0 *= z3; o0 *= z4; o0 *= z5; o0 *= z6; o0 *= z7;

    int h  = r & 15;
    int bs = r >> 4;
    int bb = bs >> 10;
    int s  = bs & 1023;
    int dst = ((bb << 4) + h) * S_LEN + s;

    float4* out = reinterpret_cast<float4*>(g_qkv + (size_t)dst * DK);
    out[0] = make_float4(o0, o1, o2, o3);
    out[1] = make_float4(o4, o5, o6, o7);
}

// ---------------------------------------------------------------------------
// Kernel 2: attention (unchanged from round 7 — passing at rel_err 7.9e-5)
// ---------------------------------------------------------------------------
__global__ __launch_bounds__(128) void attn_kernel() {
    __shared__ __align__(16) unsigned sKt[S_LEN * DK];   // 32 KB

    int head = blockIdx.x >> 3;
    int qt   = blockIdx.x & 7;
    int tid  = threadIdx.x;
    int w    = tid >> 5;
    int lane = tid & 31;
    int g    = lane >> 2;
    int t4   = lane & 3;

    const float4* Kg4 = reinterpret_cast<const float4*>(g_qkv + (size_t)head * S_LEN * DK);
#pragma unroll
    for (int i = 0; i < 8; i++) {
        int r = tid + i * 128;
        float4 f0 = Kg4[2 * r];
        float4 f1 = Kg4[2 * r + 1];
        uint4* dst = reinterpret_cast<uint4*>(sKt + r * 8);
        dst[0] = make_uint4(tf32_of(f0.x), tf32_of(f1.x), tf32_of(f0.y), tf32_of(f1.y));
        dst[1] = make_uint4(tf32_of(f0.z), tf32_of(f1.z), tf32_of(f0.w), tf32_of(f1.w));
    }
    __syncthreads();

    const float scale = 0.35355339059327373f * 1.4426950408889634f; // log2e/sqrt8

    int ar = qt * 128 + w * 32 + g;
    uint2 ra0 = *reinterpret_cast<const uint2*>(sKt + (ar     ) * 8 + 2 * t4);
    uint2 ra1 = *reinterpret_cast<const uint2*>(sKt + (ar +  8) * 8 + 2 * t4);
    uint2 ra2 = *reinterpret_cast<const uint2*>(sKt + (ar + 16) * 8 + 2 * t4);
    uint2 ra3 = *reinterpret_cast<const uint2*>(sKt + (ar + 24) * 8 + 2 * t4);
    unsigned A0[4], A1[4];
    A0[0] = tf32_of(__uint_as_float(ra0.x) * scale);
    A0[1] = tf32_of(__uint_as_float(ra1.x) * scale);
    A0[2] = tf32_of(__uint_as_float(ra0.y) * scale);
    A0[3] = tf32_of(__uint_as_float(ra1.y) * scale);
    A1[0] = tf32_of(__uint_as_float(ra2.x) * scale);
    A1[1] = tf32_of(__uint_as_float(ra3.x) * scale);
    A1[2] = tf32_of(__uint_as_float(ra2.y) * scale);
    A1[3] = tf32_of(__uint_as_float(ra3.y) * scale);

    float oc0 = 0.f, oc1 = 0.f, oc2 = 0.f, oc3 = 0.f;   // rows g, g+8
    float od0 = 0.f, od1 = 0.f, od2 = 0.f, od3 = 0.f;   // rows 16+g, 24+g
    ull lac01 = 0ull, lac23 = 0ull;

    int vidx = (g < 4) ? (2 * g) : (2 * (g - 4) + 1);
    const unsigned* vrow = sKt + vidx;

#pragma unroll 2
    for (int kb = 0; kb < S_LEN; kb += 8) {
        uint2 bb = *reinterpret_cast<const uint2*>(sKt + (kb + g) * 8 + 2 * t4);

        float c0, c1, c2, c3, d0, d1, d2, d3;
        mma8(c0, c1, c2, c3, A0[0], A0[1], A0[2], A0[3], bb.x, bb.y);
        mma8(d0, d1, d2, d3, A1[0], A1[1], A1[2], A1[3], bb.x, bb.y);

        float p0 = ex2(c0), p1 = ex2(c1), p2 = ex2(c2), p3 = ex2(c3);
        float e0 = ex2(d0), e1 = ex2(d1), e2 = ex2(d2), e3 = ex2(d3);

        unsigned vb0 = vrow[(kb + 2 * t4) * 8];
        unsigned vb1 = vrow[(kb + 2 * t4 + 1) * 8];

        mma8_acc(oc0, oc1, oc2, oc3,
                 tf32_of(p0), tf32_of(p2), tf32_of(p1), tf32_of(p3), vb0, vb1);
        mma8_acc(od0, od1, od2, od3,
                 tf32_of(e0), tf32_of(e2), tf32_of(e1), tf32_of(e3), vb0, vb1);

        lac01 = add2(lac01, add2(pack2(p0, p2), pack2(p1, p3)));
        lac23 = add2(lac23, add2(pack2(e0, e2), pack2(e1, e3)));
    }

    float lg, lg8, l16, l24;
    unpack2(lac01, lg, lg8);
    unpack2(lac23, l16, l24);
    lg  += __shfl_xor_sync(0xffffffffu, lg, 1);  lg  += __shfl_xor_sync(0xffffffffu, lg, 2);
    lg8 += __shfl_xor_sync(0xffffffffu, lg8, 1); lg8 += __shfl_xor_sync(0xffffffffu, lg8, 2);
    l16 += __shfl_xor_sync(0xffffffffu, l16, 1); l16 += __shfl_xor_sync(0xffffffffu, l16, 2);
    l24 += __shfl_xor_sync(0xffffffffu, l24, 1); l24 += __shfl_xor_sync(0xffffffffu, l24, 2);

    float r0 = 1.0f / lg, r1 = 1.0f / lg8, r2 = 1.0f / l16, r3 = 1.0f / l24;

    int bb_ = head >> 4;
    int hh  = head & 15;
    int row = qt * 128 + w * 32 + g;
    size_t base = (size_t)((bb_ << 10) + row) * E_DIM + hh * DK + 2 * t4;

    *reinterpret_cast<float2*>(g_attn + base)                = make_float2(oc0 * r0, oc1 * r0);
    *reinterpret_cast<float2*>(g_attn + base +  8 * E_DIM)   = make_float2(oc2 * r1, oc3 * r1);
    *reinterpret_cast<float2*>(g_attn + base + 16 * E_DIM)   = make_float2(od0 * r2, od1 * r2);
    *reinterpret_cast<float2*>(g_attn + base + 24 * E_DIM)   = make_float2(od2 * r3, od3 * r3);
}

// ---------------------------------------------------------------------------
// Kernel 3a: pack W into split B-fragments.
//   frag (ktile, etile), lane (g,t4): b0 = W[etile*8+g][ktile*8+t4],
//   b1 = W[..][..+4]; store uint4(b0_hi, b1_hi, b0_lo, b1_lo).
// ---------------------------------------------------------------------------
__global__ void pack_w(const float* __restrict__ W) {
    int j = blockIdx.x * blockDim.x + threadIdx.x;
    if (j >= 16 * 16 * 32) return;
    int lane = j & 31;
    int et   = (j >> 5) & 15;
    int kt   = j >> 9;
    int g    = lane >> 2;
    int t4   = lane & 3;
    int e = et * 8 + g;
    int k = kt * 8 + t4;
    float w0 = __ldg(W + e * E_DIM + k);
    float w1 = __ldg(W + e * E_DIM + k + 4);
    unsigned h0 = tf32_of(w0), h1 = tf32_of(w1);
    float l0 = w0 - __uint_as_float(h0);
    float l1 = w1 - __uint_as_float(h1);
    g_wb[j] = make_uint4(h0, h1, __float_as_uint(l0), __float_as_uint(l1));
}

// ---------------------------------------------------------------------------
// Kernel 3b: combine as split-tf32 tensor GEMM.
// Block = 64 rows x 32 e (grid 256 = 64 row-blocks x 4 e-quarters).
// A staged in shared with 132-float row pitch -> conflict-free frag LDS.
// 3 mmas per tile: ah*bh + ah*bl + al*bh  (~fp32 accuracy).
// ---------------------------------------------------------------------------
__global__ __launch_bounds__(128) void combine_kernel(float* __restrict__ out) {
    __shared__ __align__(16) float sa[64 * 132];   // ~33.8 KB

    int rb  = blockIdx.x >> 2;
    int eq  = blockIdx.x & 3;
    int row0 = rb * 64;
    int tid = threadIdx.x;
    int w   = tid >> 5;
    int lane = tid & 31;
    int g   = lane >> 2;
    int t4  = lane & 3;

    // stage 64 rows, coalesced
    const float4* src = reinterpret_cast<const float4*>(g_attn + (size_t)row0 * E_DIM);
#pragma unroll
    for (int j = 0; j < 16; j++) {
        int idx = tid + j * 128;
        int r  = idx >> 5;
        int c4 = idx & 31;
        *reinterpret_cast<float4*>(sa + r * 132 + c4 * 4) = src[idx];
    }
    __syncthreads();

    float C[4][4] = {};
    const float* sw = sa + (w * 16 + g) * 132;

#pragma unroll
    for (int kt = 0; kt < 16; kt++) {
        int kb = kt * 8;
        float a0 = sw[kb + t4];
        float a1 = sw[8 * 132 + kb + t4];
        float a2 = sw[kb + t4 + 4];
        float a3 = sw[8 * 132 + kb + t4 + 4];
        unsigned h0 = tf32_of(a0), h1 = tf32_of(a1), h2 = tf32_of(a2), h3 = tf32_of(a3);
        unsigned l0 = __float_as_uint(a0 - __uint_as_float(h0));
        unsigned l1 = __float_as_uint(a1 - __uint_as_float(h1));
        unsigned l2 = __float_as_uint(a2 - __uint_as_float(h2));
        unsigned l3 = __float_as_uint(a3 - __uint_as_float(h3));

#pragma unroll
        for (int et = 0; et < 4; et++) {
            uint4 B = __ldg(&g_wb[(kt * 16 + eq * 4 + et) * 32 + lane]);
            mma8_acc(C[et][0], C[et][1], C[et][2], C[et][3], h0, h1, h2, h3, B.x, B.y);
            mma8_acc(C[et][0], C[et][1], C[et][2], C[et][3], h0, h1, h2, h3, B.z, B.w);
            mma8_acc(C[et][0], C[et][1], C[et][2], C[et][3], l0, l1, l2, l3, B.x, B.y);
        }
    }

    int r_g = row0 + w * 16 + g;
#pragma unroll
    for (int et = 0; et < 4; et++) {
        int e0 = eq * 32 + et * 8 + 2 * t4;
        *reinterpret_cast<float2*>(out + (size_t)r_g * E_DIM + e0) =
            make_float2(C[et][0], C[et][1]);
        *reinterpret_cast<float2*>(out + (size_t)(r_g + 8) * E_DIM + e0) =
            make_float2(C[et][2], C[et][3]);
    }
}

// ---------------------------------------------------------------------------
extern "C" void kernel_launch(void* const* d_in, const int* in_sizes, int n_in,
                              void* d_out, int out_size) {
    const float* x  = nullptr;
    const float* rx = nullptr;
    const float* cw = nullptr;
    for (int i = 0; i < n_in; i++) {
        if (in_sizes[i] == NROWS * DK)          x  = (const float*)d_in[i];
        else if (in_sizes[i] == DK)             rx = (const float*)d_in[i];
        else if (in_sizes[i] == E_DIM * E_DIM)  cw = (const float*)d_in[i];
    }
    if (!x)  x  = (const float*)d_in[0];
    if (!rx) rx = (const float*)d_in[1];
    if (!cw) cw = (const float*)d_in[2];

    float* out = (float*)d_out;

    qkv_kernel<<<NROWS / 256, 256>>>(x, rx);
    pack_w<<<(16 * 16 * 32 + 255) / 256, 256>>>(cw);
    attn_kernel<<<NHEADS * 8, 128>>>();
    combine_kernel<<<256, 128>>>(out);
}